// round 1
// baseline (speedup 1.0000x reference)
#include <cuda_runtime.h>

// TensorProduct: out[b,0,n,f] = sum_{l,m} x1[b,0,l,f]*x2[b,0,m,f]*cg[l,m,n] * pe[0]
//                out[b,1,n,f] = same * pe[1]   (pe = parity_even column)
//
// Shapes: x1 (2048,1,9,512) f32, x2 (2048,1,9,512) f32, cg (9,9,25) f32,
//         parity_even (2,1) f32, out (2048,2,25,512) f32.
//
// Strategy: one thread per (b, float2-of-f). Fully unrolled contraction using the
// structural sparsity of the real-basis CG tensor (compile-time pruned ~244 terms
// instead of 2025). CG values are read at RUNTIME from shared memory, so the
// compile-time rule only needs to be a superset of the true nonzeros.

#define F2 256           // 512 floats per row = 256 float2
#define NBLK 2048        // batch

__global__ void __launch_bounds__(256)
tp_kernel(const float* __restrict__ x1,
          const float* __restrict__ x2,
          const float* __restrict__ cg,
          const float* __restrict__ pe,
          float* __restrict__ out)
{
    __shared__ float scg[9 * 9 * 25];   // 8100 B
    for (int t = threadIdx.x; t < 9 * 9 * 25; t += blockDim.x)
        scg[t] = cg[t];
    __syncthreads();

    const int g  = blockIdx.x * blockDim.x + threadIdx.x;  // 0 .. 524287
    const int f2 = g & (F2 - 1);
    const int b  = g >> 8;

    const float2* __restrict__ X1 =
        reinterpret_cast<const float2*>(x1) + (size_t)b * 9 * F2 + f2;
    const float2* __restrict__ X2 =
        reinterpret_cast<const float2*>(x2) + (size_t)b * 9 * F2 + f2;

    float2 a[9], c[9];
    #pragma unroll
    for (int l = 0; l < 9; l++) { a[l] = X1[l * F2]; }
    #pragma unroll
    for (int l = 0; l < 9; l++) { c[l] = X2[l * F2]; }

    float2 acc[25];
    #pragma unroll
    for (int n = 0; n < 25; n++) acc[n] = make_float2(0.f, 0.f);

    // Fully unrolled sparse contraction. All loop vars become compile-time
    // constants after unrolling; the guards prune structurally-zero CG entries.
    #pragma unroll
    for (int l1 = 0; l1 <= 2; l1++) {
        #pragma unroll
        for (int m1 = -2; m1 <= 2; m1++) {
            if (m1 < -l1 || m1 > l1) continue;
            const int i  = l1 * (l1 + 1) + m1;          // 0..8
            const int a1 = m1 < 0 ? -m1 : m1;
            #pragma unroll
            for (int l2 = 0; l2 <= 2; l2++) {
                #pragma unroll
                for (int m2 = -2; m2 <= 2; m2++) {
                    if (m2 < -l2 || m2 > l2) continue;
                    const int j  = l2 * (l2 + 1) + m2;   // 0..8
                    const int a2 = m2 < 0 ? -m2 : m2;

                    float2 p;
                    p.x = a[i].x * c[j].x;
                    p.y = a[i].y * c[j].y;

                    const int l3lo = (l1 > l2) ? (l1 - l2) : (l2 - l1);
                    const int l3hi = (l1 + l2) < 4 ? (l1 + l2) : 4;
                    #pragma unroll
                    for (int l3 = 0; l3 <= 4; l3++) {
                        if (l3 < l3lo || l3 > l3hi) continue;
                        #pragma unroll
                        for (int m3 = -4; m3 <= 4; m3++) {
                            if (m3 < -l3 || m3 > l3) continue;
                            const int a3 = m3 < 0 ? -m3 : m3;
                            // selection rule on |m|:
                            const bool sel = (a3 == a1 + a2) ||
                                             (a3 == a1 - a2) ||
                                             (a3 == a2 - a1);
                            // parity rule (exact real-basis CG support):
                            const int par = (l1 + l2 + l3 + a1 + a2 + a3 +
                                             (m1 < 0 ? 1 : 0) +
                                             (m2 < 0 ? 1 : 0) +
                                             (m3 < 0 ? 1 : 0)) & 1;
                            if (!sel || par) continue;

                            const int k = l3 * (l3 + 1) + m3;   // 0..24
                            const float w = scg[(i * 9 + j) * 25 + k];
                            acc[k].x = fmaf(w, p.x, acc[k].x);
                            acc[k].y = fmaf(w, p.y, acc[k].y);
                        }
                    }
                }
            }
        }
    }

    const float pe0 = pe[0];
    const float pe1 = pe[1];

    float2* __restrict__ O =
        reinterpret_cast<float2*>(out) + (size_t)b * 50 * F2 + f2;

    #pragma unroll
    for (int n = 0; n < 25; n++) {
        float2 v0 = make_float2(pe0 * acc[n].x, pe0 * acc[n].y);
        float2 v1 = make_float2(pe1 * acc[n].x, pe1 * acc[n].y);
        O[n * F2]        = v0;   // parity even plane
        O[(25 + n) * F2] = v1;   // parity odd plane (pe1 == 0 in this dataset)
    }
}

extern "C" void kernel_launch(void* const* d_in, const int* in_sizes, int n_in,
                              void* d_out, int out_size)
{
    const float* x1 = (const float*)d_in[0];
    const float* x2 = (const float*)d_in[1];
    const float* cg = (const float*)d_in[2];
    const float* pe = (const float*)d_in[3];
    float* out = (float*)d_out;

    // 2048 batches * 256 float2 lanes = 524288 threads
    tp_kernel<<<2048, 256>>>(x1, x2, cg, pe, out);
}